// round 17
// baseline (speedup 1.0000x reference)
#include <cuda_runtime.h>
#include <cuda_bf16.h>
#include <cuda_fp8.h>
#include <cstdint>
#include <math.h>

// NTXentLoss via mma.sync FP8 (e4m3) GEMM, symmetric upper-triangular tiles.
// Round 17: R16 simexp (best: STRIP=8 one-wave, fp8, 2 CTAs/SM) + norm with
// full load-hoisting (2x MLP) + loss reading only the written g_spart slots
// (row-block K touches exactly slots {I<K} U {K+8x}).

#define M_TOTAL 8192
#define N_HALF  4096
#define DDIM    256
#define RT      128
#define NT64    (M_TOTAL / RT)           // 64 tile blocks
#define STRIP   8
#define SMS_B   272                      // fp8 tile row stride: 256 B + 16 pad
#define SQRT_L2E2 1.6986441f             // sqrt(2/ln2); dot = 2*log2e*sim

// Scratch (__device__ globals: allocation-free rule)
__device__ uint8_t g_Z[M_TOTAL * DDIM];             // normalized*s, e4m3
__device__ float g_pos[M_TOTAL];                    // 2*sim[i, pair] (fp32)
__device__ float g_spart[NT64][M_TOTAL];            // partial sums, slot-unique
__device__ float g_red[NT64];                       // loss block partials
__device__ unsigned int g_ctr;                      // loss completion counter

// smem layout (bytes) — total ~105 KB -> 2 CTAs/SM
#define SM_A    0
#define SM_B0   (RT * SMS_B)             // 34816
#define SM_B1   (2 * RT * SMS_B)         // 69632
#define SM_CSC  (3 * RT * SMS_B)         // 104448: csc[4][2][32] floats
#define SMEM_BYTES (SM_CSC + 4 * 2 * 32 * 4)   // 105472

// ---------------- PTX helpers (compute_103-safe subset) ----------------
__device__ __forceinline__ uint32_t smem_to_u32(const void* p) {
    uint32_t a;
    asm("{ .reg .u64 t; cvta.to.shared.u64 t, %1; cvt.u32.u64 %0, t; }"
        : "=r"(a) : "l"(p));
    return a;
}
__device__ __forceinline__ void ldsm4(uint32_t* r, uint32_t addr) {
    asm volatile("ldmatrix.sync.aligned.m8n8.x4.shared.b16 {%0,%1,%2,%3}, [%4];"
                 : "=r"(r[0]), "=r"(r[1]), "=r"(r[2]), "=r"(r[3]) : "r"(addr));
}
__device__ __forceinline__ void mma16832(float* d, const uint32_t* a, const uint32_t* b) {
    asm volatile(
        "mma.sync.aligned.m16n8k32.row.col.f32.e4m3.e4m3.f32 "
        "{%0,%1,%2,%3}, {%4,%5,%6,%7}, {%8,%9}, {%0,%1,%2,%3};"
        : "+f"(d[0]), "+f"(d[1]), "+f"(d[2]), "+f"(d[3])
        : "r"(a[0]), "r"(a[1]), "r"(a[2]), "r"(a[3]), "r"(b[0]), "r"(b[1]));
}
__device__ __forceinline__ void cp16(uint32_t smaddr, const void* gptr) {
    asm volatile("cp.async.cg.shared.global [%0], [%1], 16;"
                 :: "r"(smaddr), "l"(gptr) : "memory");
}
#define CP_COMMIT() asm volatile("cp.async.commit_group;" ::: "memory")
template <int N>
__device__ __forceinline__ void cp_wait() {
    asm volatile("cp.async.wait_group %0;" :: "n"(N) : "memory");
}
__device__ __forceinline__ void barpair(int id) {    // 2-warp named barrier
    asm volatile("bar.sync %0, 64;" :: "r"(id) : "memory");
}
__device__ __forceinline__ float ex2(float x) {
    float r;
    asm("ex2.approx.f32 %0, %1;" : "=f"(r) : "f"(x));
    return r;
}

// Async-copy one 128x256-byte fp8 tile into smem (2048 16B chunks, 256 thr).
__device__ __forceinline__ void cp_tile(uint32_t smb, int smoff, int row0) {
    const int tid = threadIdx.x;
    #pragma unroll
    for (int it = 0; it < 8; ++it) {
        int idx = it * 256 + tid;
        int r = idx >> 4;
        int c = idx & 15;
        cp16(smb + smoff + r * SMS_B + c * 16,
             g_Z + (size_t)(row0 + r) * DDIM + c * 16);
    }
}

// ---------------------------------------------------------------------------
// Kernel A: normalize, scale by sqrt(2*log2e), e4m3 quantize; fused pos dot.
// Two pairs per warp; ALL loads hoisted before any reduction (2x MLP).
// ---------------------------------------------------------------------------
__global__ __launch_bounds__(256) void norm_kernel(const float* __restrict__ zis,
                                                   const float* __restrict__ zjs)
{
    const int wid = threadIdx.x >> 5, lane = threadIdx.x & 31;
    const int i0 = blockIdx.x * 16 + wid * 2;           // pairs i0, i0+1
    const int i1 = i0 + 1;

    // Hoisted loads: 16 float4 (both pairs, both halves of each row)
    const float4* J0 = reinterpret_cast<const float4*>(zjs + (size_t)i0 * DDIM);
    const float4* I0 = reinterpret_cast<const float4*>(zis + (size_t)i0 * DDIM);
    const float4* J1 = reinterpret_cast<const float4*>(zjs + (size_t)i1 * DDIM);
    const float4* I1 = reinterpret_cast<const float4*>(zis + (size_t)i1 * DDIM);
    float4 ja0 = J0[lane],      jb0 = J0[lane + 32];
    float4 ia0 = I0[lane],      ib0 = I0[lane + 32];
    float4 ja1 = J1[lane],      jb1 = J1[lane + 32];
    float4 ia1 = I1[lane],      ib1 = I1[lane + 32];

    // Pair 0 partials
    float ssj0 = ja0.x*ja0.x + ja0.y*ja0.y + ja0.z*ja0.z + ja0.w*ja0.w
               + jb0.x*jb0.x + jb0.y*jb0.y + jb0.z*jb0.z + jb0.w*jb0.w;
    float ssi0 = ia0.x*ia0.x + ia0.y*ia0.y + ia0.z*ia0.z + ia0.w*ia0.w
               + ib0.x*ib0.x + ib0.y*ib0.y + ib0.z*ib0.z + ib0.w*ib0.w;
    float dot0 = ja0.x*ia0.x + ja0.y*ia0.y + ja0.z*ia0.z + ja0.w*ia0.w
               + jb0.x*ib0.x + jb0.y*ib0.y + jb0.z*ib0.z + jb0.w*ib0.w;
    // Pair 1 partials
    float ssj1 = ja1.x*ja1.x + ja1.y*ja1.y + ja1.z*ja1.z + ja1.w*ja1.w
               + jb1.x*jb1.x + jb1.y*jb1.y + jb1.z*jb1.z + jb1.w*jb1.w;
    float ssi1 = ia1.x*ia1.x + ia1.y*ia1.y + ia1.z*ia1.z + ia1.w*ia1.w
               + ib1.x*ib1.x + ib1.y*ib1.y + ib1.z*ib1.z + ib1.w*ib1.w;
    float dot1 = ja1.x*ia1.x + ja1.y*ia1.y + ja1.z*ia1.z + ja1.w*ia1.w
               + jb1.x*ib1.x + jb1.y*ib1.y + jb1.z*ib1.z + jb1.w*ib1.w;

    #pragma unroll
    for (int o = 16; o > 0; o >>= 1) {
        ssj0 += __shfl_xor_sync(0xffffffffu, ssj0, o);
        ssi0 += __shfl_xor_sync(0xffffffffu, ssi0, o);
        dot0 += __shfl_xor_sync(0xffffffffu, dot0, o);
        ssj1 += __shfl_xor_sync(0xffffffffu, ssj1, o);
        ssi1 += __shfl_xor_sync(0xffffffffu, ssi1, o);
        dot1 += __shfl_xor_sync(0xffffffffu, dot1, o);
    }
    float invj0 = 1.0f / fmaxf(sqrtf(ssj0), 1e-8f);
    float invi0 = 1.0f / fmaxf(sqrtf(ssi0), 1e-8f);
    float invj1 = 1.0f / fmaxf(sqrtf(ssj1), 1e-8f);
    float invi1 = 1.0f / fmaxf(sqrtf(ssi1), 1e-8f);
    if (lane == 0) {
        float p0 = 2.0f * dot0 * invi0 * invj0;
        float p1 = 2.0f * dot1 * invi1 * invj1;
        g_pos[i0] = p0;  g_pos[i0 + N_HALF] = p0;
        g_pos[i1] = p1;  g_pos[i1 + N_HALF] = p1;
    }
    const float qj0 = invj0 * SQRT_L2E2, qi0 = invi0 * SQRT_L2E2;
    const float qj1 = invj1 * SQRT_L2E2, qi1 = invi1 * SQRT_L2E2;

    uint32_t* dj0 = reinterpret_cast<uint32_t*>(g_Z + (size_t)i0 * DDIM);
    uint32_t* di0 = reinterpret_cast<uint32_t*>(g_Z + (size_t)(i0 + N_HALF) * DDIM);
    uint32_t* dj1 = reinterpret_cast<uint32_t*>(g_Z + (size_t)i1 * DDIM);
    uint32_t* di1 = reinterpret_cast<uint32_t*>(g_Z + (size_t)(i1 + N_HALF) * DDIM);
    __nv_fp8x4_e4m3 a0(make_float4(ja0.x*qj0, ja0.y*qj0, ja0.z*qj0, ja0.w*qj0));
    __nv_fp8x4_e4m3 a1(make_float4(jb0.x*qj0, jb0.y*qj0, jb0.z*qj0, jb0.w*qj0));
    __nv_fp8x4_e4m3 a2(make_float4(ia0.x*qi0, ia0.y*qi0, ia0.z*qi0, ia0.w*qi0));
    __nv_fp8x4_e4m3 a3(make_float4(ib0.x*qi0, ib0.y*qi0, ib0.z*qi0, ib0.w*qi0));
    __nv_fp8x4_e4m3 a4(make_float4(ja1.x*qj1, ja1.y*qj1, ja1.z*qj1, ja1.w*qj1));
    __nv_fp8x4_e4m3 a5(make_float4(jb1.x*qj1, jb1.y*qj1, jb1.z*qj1, jb1.w*qj1));
    __nv_fp8x4_e4m3 a6(make_float4(ia1.x*qi1, ia1.y*qi1, ia1.z*qi1, ia1.w*qi1));
    __nv_fp8x4_e4m3 a7(make_float4(ib1.x*qi1, ib1.y*qi1, ib1.z*qi1, ib1.w*qi1));
    dj0[lane]      = *reinterpret_cast<uint32_t*>(&a0);
    dj0[lane + 32] = *reinterpret_cast<uint32_t*>(&a1);
    di0[lane]      = *reinterpret_cast<uint32_t*>(&a2);
    di0[lane + 32] = *reinterpret_cast<uint32_t*>(&a3);
    dj1[lane]      = *reinterpret_cast<uint32_t*>(&a4);
    dj1[lane + 32] = *reinterpret_cast<uint32_t*>(&a5);
    di1[lane]      = *reinterpret_cast<uint32_t*>(&a6);
    di1[lane + 32] = *reinterpret_cast<uint32_t*>(&a7);
}

// ---------------------------------------------------------------------------
// Kernel B: strip of up to 8 upper-tri tiles per CTA. Static grid (8, 64):
// 288 active CTAs -> ONE wave at 2 CTAs/SM. R16 verbatim.
// ---------------------------------------------------------------------------
__global__ __launch_bounds__(256, 2) void simexp_kernel()
{
    const int I = blockIdx.y;
    const int J0 = I + STRIP * blockIdx.x;
    if (J0 >= NT64) return;
    const int nt = min(STRIP, NT64 - J0);

    extern __shared__ char sm[];
    const uint32_t smb = smem_to_u32(sm);
    const int tid = threadIdx.x;
    const int wid = tid >> 5;
    const int lane = tid & 31;
    const int wm = wid >> 2;              // 0..1 (M)
    const int wn = wid & 3;               // 0..3 (N)
    const int rb = I * RT;

    const int a_row  = wm * 64 + (lane & 7) + ((lane >> 3) & 1) * 8;
    const int a_kadB = (lane >> 4) * 16;
    const int b_row  = wn * 32 + (lane & 7) + ((lane >> 4) & 1) * 8;
    const int b_kadB = ((lane >> 3) & 1) * 16;

    const uint32_t smA = smb + SM_A;
    float* csc = reinterpret_cast<float*>(sm + SM_CSC);   // [4 wn][2 wm][32]

    cp_tile(smb, SM_A, rb);
    if (J0 != I) cp_tile(smb, SM_B0, J0 * RT);
    CP_COMMIT();

    const int qrow = lane >> 2;
    const int drow0 = rb + wm * 64 + qrow;

    float rsum[8];
    #pragma unroll
    for (int q = 0; q < 8; ++q) rsum[q] = 0.f;

    int buf = 0;
    for (int s = 0; s < nt; ++s) {
        const int J = J0 + s;
        const int cb = J * RT;
        const bool diagT = (J == I);

        cp_wait<0>();
        __syncthreads();

        if (s + 1 < nt) {
            cp_tile(smb, (buf ^ 1) ? SM_B1 : SM_B0, (J + 1) * RT);
            CP_COMMIT();
        }

        const uint32_t smB = diagT ? smA : (smb + (buf ? SM_B1 : SM_B0));

        float d[4][4][4];
        #pragma unroll
        for (int mf = 0; mf < 4; ++mf)
            #pragma unroll
            for (int nf = 0; nf < 4; ++nf)
                #pragma unroll
                for (int e = 0; e < 4; ++e) d[mf][nf][e] = 0.f;

        #pragma unroll
        for (int ks = 0; ks < DDIM / 32; ++ks) {
            const int k0b = ks * 32;
            uint32_t a[4][4];
            #pragma unroll
            for (int mf = 0; mf < 4; ++mf)
                ldsm4(a[mf], smA + (uint32_t)(a_row + mf * 16) * SMS_B
                                 + (uint32_t)(k0b + a_kadB));
            #pragma unroll
            for (int nh = 0; nh < 2; ++nh) {
                uint32_t r4[4];
                ldsm4(r4, smB + (uint32_t)(b_row + nh * 16) * SMS_B
                              + (uint32_t)(k0b + b_kadB));
                #pragma unroll
                for (int mf = 0; mf < 4; ++mf) {
                    mma16832(d[mf][2*nh],     a[mf], r4);
                    mma16832(d[mf][2*nh + 1], a[mf], r4 + 2);
                }
            }
        }

        const int dcol0 = cb + wn * 32 + 2 * (lane & 3);
        float csum[8];
        #pragma unroll
        for (int q = 0; q < 8; ++q) csum[q] = 0.f;

        #pragma unroll
        for (int mf = 0; mf < 4; ++mf) {
            const int r0 = drow0 + mf * 16;
            #pragma unroll
            for (int nf = 0; nf < 4; ++nf) {
                const int c0 = dcol0 + nf * 8;
                float e0 = ex2(d[mf][nf][0]);
                float e1 = ex2(d[mf][nf][1]);
                float e2 = ex2(d[mf][nf][2]);
                float e3 = ex2(d[mf][nf][3]);
                if (diagT) {
                    if (c0     == r0    ) e0 = 0.f;
                    if (c0 + 1 == r0    ) e1 = 0.f;
                    if (c0     == r0 + 8) e2 = 0.f;
                    if (c0 + 1 == r0 + 8) e3 = 0.f;
                }
                rsum[mf*2]   += e0 + e1;
                rsum[mf*2+1] += e2 + e3;
                csum[nf*2]   += e0 + e2;
                csum[nf*2+1] += e1 + e3;
            }
        }

        if (!diagT) {
            #pragma unroll
            for (int q = 0; q < 8; ++q) {
                float w = csum[q];
                w += __shfl_xor_sync(0xffffffffu, w, 4);
                w += __shfl_xor_sync(0xffffffffu, w, 8);
                w += __shfl_xor_sync(0xffffffffu, w, 16);
                csum[q] = w;
            }
            float* my = csc + (wn * 2 + wm) * 32;
            if (lane < 4) {
                #pragma unroll
                for (int nf = 0; nf < 4; ++nf)
                    #pragma unroll
                    for (int e2 = 0; e2 < 2; ++e2)
                        my[nf * 8 + 2 * lane + e2] = csum[nf*2+e2];
            }
            barpair(1 + wn);
            if (wm == 1) {
                float v = csc[(wn*2+0)*32 + lane] + csc[(wn*2+1)*32 + lane];
                g_spart[I][cb + wn * 32 + lane] = v;
            }
        }

        if (s + 1 < nt) buf ^= 1;
    }

    #pragma unroll
    for (int q = 0; q < 8; ++q) {
        float v = rsum[q];
        v += __shfl_xor_sync(0xffffffffu, v, 1);
        v += __shfl_xor_sync(0xffffffffu, v, 2);
        rsum[q] = v;
    }
    __syncthreads();
    float* redR = reinterpret_cast<float*>(sm);          // [4 wn][128]
    if ((lane & 3) == 0) {
        #pragma unroll
        for (int mf = 0; mf < 4; ++mf)
            #pragma unroll
            for (int h = 0; h < 2; ++h)
                redR[wn * RT + wm * 64 + mf * 16 + h * 8 + qrow] = rsum[mf*2+h];
    }
    __syncthreads();
    if (tid < RT) {
        float rs = redR[tid] + redR[RT+tid] + redR[2*RT+tid] + redR[3*RT+tid];
        g_spart[J0][rb + tid] = rs;
    }
}

// ---------------------------------------------------------------------------
// Kernel D: loss; 64 blocks (one per row-block K), reads ONLY written slots:
// col-slots {I : I < K} and row-slots {K + 8x}. Threadfence final reduce.
// ---------------------------------------------------------------------------
__global__ __launch_bounds__(128) void loss_kernel(float* __restrict__ out)
{
    __shared__ float red[4];
    __shared__ bool amLast;
    const int K = blockIdx.x;
    const int tid = threadIdx.x;
    const int i = K * RT + tid;

    float s = 0.f;
    for (int t = 0; t < K; ++t)             // col-slot writers
        s += g_spart[t][i];
    for (int t = K; t < NT64; t += STRIP)   // row-slot writers
        s += g_spart[t][i];
    float acc = __logf(s) - g_pos[i];
    #pragma unroll
    for (int o = 16; o > 0; o >>= 1)
        acc += __shfl_xor_sync(0xffffffffu, acc, o);
    if ((tid & 31) == 0) red[tid >> 5] = acc;
    __syncthreads();
    if (tid == 0) {
        g_red[K] = red[0] + red[1] + red[2] + red[3];
        __threadfence();
        unsigned int v = atomicAdd(&g_ctr, 1u);
        amLast = (v == (unsigned)(NT64 - 1));
    }
    __syncthreads();
    if (amLast && tid < 32) {
        float v = g_red[tid] + g_red[tid + 32];
        #pragma unroll
        for (int o = 16; o > 0; o >>= 1)
            v += __shfl_xor_sync(0xffffffffu, v, o);
        if (tid == 0) {
            out[0] = v / (float)M_TOTAL;
            g_ctr = 0u;                     // reset for next graph replay
        }
    }
}

// ---------------------------------------------------------------------------
extern "C" void kernel_launch(void* const* d_in, const int* in_sizes, int n_in,
                              void* d_out, int out_size)
{
    const float* zis = (const float*)d_in[0];
    const float* zjs = (const float*)d_in[1];
    float* out = (float*)d_out;

    norm_kernel<<<N_HALF / 16, 256>>>(zis, zjs);

    cudaFuncSetAttribute(simexp_kernel,
                         cudaFuncAttributeMaxDynamicSharedMemorySize, SMEM_BYTES);
    simexp_kernel<<<dim3(8, NT64), 256, SMEM_BYTES>>>();

    loss_kernel<<<NT64, 128>>>(out);
}